// round 14
// baseline (speedup 1.0000x reference)
#include <cuda_runtime.h>
#include <cstdint>

// Problem constants
#define B_ROWS   65536
#define K1       1024
#define K2       512
#define K3       768
#define NPAIRS   1152                  // (K1+K2+K3)/2
#define RANK     10
#define OUTDIM   512

#define T1       512
#define GRID1    152                   // 1 CTA/SM
#define NWARPS   (GRID1 * (T1 / 32))   // 2432
#define NGROUPS  (B_ROWS / 4)          // 16384 groups of 4 rows

#define FS_ELEMS (RANK * NPAIRS)       // 11520 float2
#define FS_BYTES (FS_ELEMS * 8)        // 92160
#define FO_ELEMS (OUTDIM * (RANK / 2)) // 2560 u64
#define FO_BYTES (FO_ELEMS * 8)        // 20480
#define RING_BYTES 4096                // 4 slots x 1KB per warp
#define SMEM1    (FS_BYTES + FO_BYTES + (T1 / 32) * RING_BYTES)  // 178176

// chunk counts (64-float / 256-byte chunks per row)
#define NC1      (K1 / 64)             // 16
#define NC2      (K2 / 64)             // 8
#define NC3      (K3 / 64)             // 12

typedef unsigned long long u64;

// ---------- f32x2 packed helpers ----------
__device__ __forceinline__ u64 pk2(float lo, float hi) {
    u64 r; asm("mov.b64 %0, {%1, %2};" : "=l"(r) : "f"(lo), "f"(hi)); return r;
}
__device__ __forceinline__ void upk2(u64 v, float& lo, float& hi) {
    asm("mov.b64 {%0, %1}, %2;" : "=f"(lo), "=f"(hi) : "l"(v));
}
__device__ __forceinline__ u64 fma2(u64 a, u64 b, u64 c) {
    u64 d; asm("fma.rn.f32x2 %0, %1, %2, %3;" : "=l"(d) : "l"(a), "l"(b), "l"(c));
    return d;
}
__device__ __forceinline__ float hadd2(u64 v) {
    float lo, hi; upk2(v, lo, hi); return lo + hi;
}
__device__ __forceinline__ ulonglong2 lds128(uint32_t a) {
    ulonglong2 v;
    asm volatile("ld.shared.v2.u64 {%0, %1}, [%2];"
                 : "=l"(v.x), "=l"(v.y) : "r"(a));
    return v;
}

#define CP16(DST, SRC) \
    asm volatile("cp.async.cg.shared.global [%0], [%1], 16;" \
                 :: "r"(DST), "l"(SRC) : "memory")

// issue one 1KB chunk (4 rows x 256B): this lane copies 16B of each of its
// 2 rows (rows 2h, 2h+1) into ring slot SLOT, then commits a group.
#define ISSUE(LO, HI, C, SLOT) do {                                       \
    uint32_t _d = stage_base + (uint32_t)(SLOT) * 1024u + dstoff;         \
    CP16(_d,        (LO) + (size_t)(C) * 256);                            \
    CP16(_d + 256u, (HI) + (size_t)(C) * 256);                            \
    asm volatile("cp.async.commit_group;" ::: "memory");                  \
} while (0)

#define WAITG2() asm volatile("cp.async.wait_group 2;" ::: "memory")

// consume ring slot SLOT against factor pointer FP (10 LDS.128 + 40 fma2)
#define CONSUME(SLOT, FP) do {                                            \
    uint32_t _s = stage_base + (uint32_t)(SLOT) * 1024u + dstoff;         \
    ulonglong2 vA = lds128(_s);                                           \
    ulonglong2 vB = lds128(_s + 256u);                                    \
    const ulonglong2* _fp = (FP);                                         \
    _Pragma("unroll")                                                     \
    for (int j = 0; j < RANK; j++) {                                      \
        ulonglong2 fv = _fp[j * (NPAIRS / 2)];                            \
        acc[0][j] = fma2(vA.x, fv.x, acc[0][j]);                          \
        acc[0][j] = fma2(vA.y, fv.y, acc[0][j]);                          \
        acc[1][j] = fma2(vB.x, fv.x, acc[1][j]);                          \
        acc[1][j] = fma2(vB.y, fv.y, acc[1][j]);                          \
    }                                                                     \
} while (0)

// fold even/odd halves of acc into zt, zero acc
#define FOLD() do {                                                       \
    _Pragma("unroll") for (int i = 0; i < 2; i++)                         \
    _Pragma("unroll") for (int j = 0; j < RANK; j++) {                    \
        zt[i][j] = hadd2(acc[i][j]); acc[i][j] = 0ull; }                  \
} while (0)

// butterfly-reduce zt over the 16-lane k-group (stays within each half)
#define REDUCE() do {                                                     \
    _Pragma("unroll") for (int m = 8; m > 0; m >>= 1)                     \
    _Pragma("unroll") for (int i = 0; i < 2; i++)                         \
    _Pragma("unroll") for (int j = 0; j < RANK; j++)                      \
        zt[i][j] += __shfl_xor_sync(0xffffffffu, zt[i][j], m);            \
} while (0)

extern "C" __global__ void __launch_bounds__(T1, 1)
arf_fused(const float* __restrict__ x1, const float* __restrict__ x2,
          const float* __restrict__ x3,
          const float* __restrict__ f1, const float* __restrict__ f2g,
          const float* __restrict__ f3, const float* __restrict__ fout,
          float* __restrict__ out)
{
    extern __shared__ __align__(16) float2 f_s[];   // factors | fout | rings

    const int tid = threadIdx.x;

    // factor repack: f_s[r*NPAIRS + kp] = (f_seg[2k][r], f_seg[2k+1][r])
    for (int idx = tid; idx < FS_ELEMS; idx += T1) {
        int r  = idx / NPAIRS;
        int kp = idx % NPAIRS;
        const float* f; int kloc;
        if (kp < K1 / 2)              { f = f1;  kloc = 2 * kp; }
        else if (kp < (K1 + K2) / 2)  { f = f2g; kloc = 2 * (kp - K1 / 2); }
        else                          { f = f3;  kloc = 2 * (kp - (K1 + K2) / 2); }
        f_s[idx] = make_float2(f[kloc * RANK + r], f[(kloc + 1) * RANK + r]);
    }
    // fout: raw float2 view (rank pairs), after the factor area
    float2* fo_s = f_s + FS_ELEMS;
    const float2* fo_g = reinterpret_cast<const float2*>(fout);
    for (int idx = tid; idx < FO_ELEMS; idx += T1) fo_s[idx] = fo_g[idx];
    __syncthreads();

    const ulonglong2* fsp  = reinterpret_cast<const ulonglong2*>(f_s);
    const u64*        fo64 = reinterpret_cast<const u64*>(fo_s);

    const int lane = tid & 31;
    const int kL   = lane & 15;
    const int h    = lane >> 4;            // half-warp: owns rows 2h, 2h+1
    const int wid  = tid >> 5;
    const int gw   = blockIdx.x * (T1 / 32) + wid;

    const uint32_t stage_base =
        (uint32_t)__cvta_generic_to_shared((char*)f_s + FS_BYTES + FO_BYTES
                                           + wid * RING_BYTES);
    const uint32_t dstoff = (uint32_t)(h * 512 + kL * 16);

    // factor bases (ulonglong2 units) for this lane's k position
    const ulonglong2* FA = fsp + kL;                          // seg1
    const ulonglong2* FB = FA + (K1 / 2) / 2;                 // seg2 (+256)
    const ulonglong2* FC = FA + ((K1 + K2) / 2) / 2;          // seg3 (+384)

    u64 acc[2][RANK];
#pragma unroll
    for (int i = 0; i < 2; i++)
#pragma unroll
        for (int j = 0; j < RANK; j++) acc[i][j] = 0ull;

    float p[2][RANK], zt[2][RANK];

    // prologue: first group's x1 chunks 0..2 into slots 0..2
    const char* rA  = (const char*)x1 + ((size_t)(gw * 4 + 2 * h) * K1) * 4 + kL * 16;
    const char* rA2 = rA + (size_t)K1 * 4;
    ISSUE(rA, rA2, 0, 0);
    ISSUE(rA, rA2, 1, 1);
    ISSUE(rA, rA2, 2, 2);

    for (int g = gw; g < NGROUPS; g += NWARPS) {
        const int row0 = g * 4;
        const int gn   = (g + NWARPS < NGROUPS) ? g + NWARPS : g;

        const char* rB  = (const char*)x2 + ((size_t)(row0 + 2 * h) * K2) * 4 + kL * 16;
        const char* rB2 = rB + (size_t)K2 * 4;
        const char* rC  = (const char*)x3 + ((size_t)(row0 + 2 * h) * K3) * 4 + kL * 16;
        const char* rC2 = rC + (size_t)K3 * 4;
        const char* rN  = (const char*)x1 + ((size_t)(gn * 4 + 2 * h) * K1) * 4 + kL * 16;
        const char* rN2 = rN + (size_t)K1 * 4;

        // ---- segment 1 (x1): chunks 0..15 ----
#pragma unroll
        for (int c = 0; c < NC1; c++) {
            WAITG2();
            CONSUME(c & 3, FA + c * 16);
            if (c < NC1 - 3) ISSUE(rA, rA2, c + 3,       (c + 3) & 3);
            else             ISSUE(rB, rB2, c - (NC1-3), (c + 3) & 3);
        }
        FOLD(); REDUCE();                      // pipeline stays full underneath
#pragma unroll
        for (int i = 0; i < 2; i++)
#pragma unroll
            for (int j = 0; j < RANK; j++) p[i][j] = zt[i][j];

        // ---- segment 2 (x2) ----
#pragma unroll
        for (int c = 0; c < NC2; c++) {
            WAITG2();
            CONSUME((NC1 + c) & 3, FB + c * 16);
            if (c < NC2 - 3) ISSUE(rB, rB2, c + 3,       (NC1 + c + 3) & 3);
            else             ISSUE(rC, rC2, c - (NC2-3), (NC1 + c + 3) & 3);
        }
        FOLD(); REDUCE();
#pragma unroll
        for (int i = 0; i < 2; i++)
#pragma unroll
            for (int j = 0; j < RANK; j++) p[i][j] *= zt[i][j];

        // ---- segment 3 (x3): leads into next group's x1 ----
#pragma unroll
        for (int c = 0; c < NC3; c++) {
            WAITG2();
            CONSUME((NC1 + NC2 + c) & 3, FC + c * 16);
            if (c < NC3 - 3) ISSUE(rC, rC2, c + 3,       (NC1 + NC2 + c + 3) & 3);
            else             ISSUE(rN, rN2, c - (NC3-3), (NC1 + NC2 + c + 3) & 3);
        }
        FOLD(); REDUCE();
#pragma unroll
        for (int i = 0; i < 2; i++)
#pragma unroll
            for (int j = 0; j < RANK; j++) p[i][j] *= zt[i][j];

        rA = rN; rA2 = rN2;

        // ---- fused epilogue: out[2h..2h+1 rows] = p @ fout^T ----
        // Runs while the next group's 3 chunks are in flight.
        u64 yp0[RANK / 2], yp1[RANK / 2];
#pragma unroll
        for (int j = 0; j < RANK / 2; j++) {
            yp0[j] = pk2(p[0][2 * j], p[0][2 * j + 1]);
            yp1[j] = pk2(p[1][2 * j], p[1][2 * j + 1]);
        }
        float* o0 = out + (size_t)(row0 + 2 * h) * OUTDIM;
        float* o1 = o0 + OUTDIM;
#pragma unroll
        for (int i = 0; i < 8; i++) {
            const int cb = 4 * (16 * i + kL);   // this lane's col quad
            float4 r0, r1;
            float* r0p = &r0.x;
            float* r1p = &r1.x;
#pragma unroll
            for (int cc = 0; cc < 4; cc++) {
                u64 a0 = 0ull, a1 = 0ull;
#pragma unroll
                for (int j = 0; j < RANK / 2; j++) {
                    u64 fv = fo64[(cb + cc) * (RANK / 2) + j];  // dedup'd LDS.64
                    a0 = fma2(yp0[j], fv, a0);
                    a1 = fma2(yp1[j], fv, a1);
                }
                r0p[cc] = hadd2(a0);
                r1p[cc] = hadd2(a1);
            }
            *reinterpret_cast<float4*>(o0 + cb) = r0;   // STG.128, coalesced/half
            *reinterpret_cast<float4*>(o1 + cb) = r1;
        }
    }

    asm volatile("cp.async.wait_group 0;" ::: "memory");   // drain
}

extern "C" void kernel_launch(void* const* d_in, const int* in_sizes, int n_in,
                              void* d_out, int out_size)
{
    const float* x1   = (const float*)d_in[0];
    const float* x2   = (const float*)d_in[1];
    const float* x3   = (const float*)d_in[2];
    const float* f1   = (const float*)d_in[3];
    const float* f2   = (const float*)d_in[4];
    const float* f3   = (const float*)d_in[5];
    const float* fout = (const float*)d_in[6];
    float* out = (float*)d_out;

    cudaFuncSetAttribute(arf_fused,
                         cudaFuncAttributeMaxDynamicSharedMemorySize, SMEM1);

    arf_fused<<<GRID1, T1, SMEM1>>>(x1, x2, x3, f1, f2, f3, fout, out);
}

// round 15
// speedup vs baseline: 1.0759x; 1.0759x over previous
#include <cuda_runtime.h>
#include <cstdint>

// Problem constants
#define B_ROWS   65536
#define K1       1024
#define K2       512
#define K3       768
#define NPAIRS   1152                  // (K1+K2+K3)/2
#define RANK     10
#define OUTDIM   512

#define T1       512
#define GRID1    152                   // 1 CTA/SM
#define NWARPS   (GRID1 * (T1 / 32))   // 2432
#define NGROUPS  (B_ROWS / 4)          // 16384 groups of 4 rows

#define FS_ELEMS (RANK * NPAIRS)       // 11520 float2
#define FS_BYTES (FS_ELEMS * 8)        // 92160
#define FO_ELEMS (OUTDIM * (RANK / 2)) // 2560 u64
#define FO_BYTES (FO_ELEMS * 8)        // 20480
#define RING_BYTES 4096                // 4 slots x 1KB per warp
#define SMEM1    (FS_BYTES + FO_BYTES + (T1 / 32) * RING_BYTES)  // 178176

// chunk counts (64-float / 256-byte chunks per row)
#define NC1      (K1 / 64)             // 16
#define NC2      (K2 / 64)             // 8
#define NC3      (K3 / 64)             // 12

typedef unsigned long long u64;

// ---------- f32x2 packed helpers ----------
__device__ __forceinline__ u64 pk2(float lo, float hi) {
    u64 r; asm("mov.b64 %0, {%1, %2};" : "=l"(r) : "f"(lo), "f"(hi)); return r;
}
__device__ __forceinline__ void upk2(u64 v, float& lo, float& hi) {
    asm("mov.b64 {%0, %1}, %2;" : "=f"(lo), "=f"(hi) : "l"(v));
}
__device__ __forceinline__ u64 fma2(u64 a, u64 b, u64 c) {
    u64 d; asm("fma.rn.f32x2 %0, %1, %2, %3;" : "=l"(d) : "l"(a), "l"(b), "l"(c));
    return d;
}
__device__ __forceinline__ float hadd2(u64 v) {
    float lo, hi; upk2(v, lo, hi); return lo + hi;
}
__device__ __forceinline__ ulonglong2 lds128(uint32_t a) {
    ulonglong2 v;
    asm volatile("ld.shared.v2.u64 {%0, %1}, [%2];"
                 : "=l"(v.x), "=l"(v.y) : "r"(a));
    return v;
}

#define CP16(DST, SRC) \
    asm volatile("cp.async.cg.shared.global [%0], [%1], 16;" \
                 :: "r"(DST), "l"(SRC) : "memory")

// issue one 1KB chunk (4 rows x 256B): this lane copies 16B of each of its
// 2 rows (rows 2h, 2h+1) into ring slot SLOT, then commits a group.
#define ISSUE(LO, HI, C, SLOT) do {                                       \
    uint32_t _d = stage_base + (uint32_t)(SLOT) * 1024u + dstoff;         \
    CP16(_d,        (LO) + (size_t)(C) * 256);                            \
    CP16(_d + 256u, (HI) + (size_t)(C) * 256);                            \
    asm volatile("cp.async.commit_group;" ::: "memory");                  \
} while (0)

#define WAITG2() asm volatile("cp.async.wait_group 2;" ::: "memory")

// consume ring slot SLOT against factor pointer FP (10 LDS.128 + 40 fma2)
#define CONSUME(SLOT, FP) do {                                            \
    uint32_t _s = stage_base + (uint32_t)(SLOT) * 1024u + dstoff;         \
    ulonglong2 vA = lds128(_s);                                           \
    ulonglong2 vB = lds128(_s + 256u);                                    \
    const ulonglong2* _fp = (FP);                                         \
    _Pragma("unroll")                                                     \
    for (int j = 0; j < RANK; j++) {                                      \
        ulonglong2 fv = _fp[j * (NPAIRS / 2)];                            \
        acc[0][j] = fma2(vA.x, fv.x, acc[0][j]);                          \
        acc[0][j] = fma2(vA.y, fv.y, acc[0][j]);                          \
        acc[1][j] = fma2(vB.x, fv.x, acc[1][j]);                          \
        acc[1][j] = fma2(vB.y, fv.y, acc[1][j]);                          \
    }                                                                     \
} while (0)

// fold even/odd halves of acc into zt, zero acc
#define FOLD() do {                                                       \
    _Pragma("unroll") for (int i = 0; i < 2; i++)                         \
    _Pragma("unroll") for (int j = 0; j < RANK; j++) {                    \
        zt[i][j] = hadd2(acc[i][j]); acc[i][j] = 0ull; }                  \
} while (0)

// butterfly-reduce zt over the 16-lane k-group (stays within each half)
#define REDUCE() do {                                                     \
    _Pragma("unroll") for (int m = 8; m > 0; m >>= 1)                     \
    _Pragma("unroll") for (int i = 0; i < 2; i++)                         \
    _Pragma("unroll") for (int j = 0; j < RANK; j++)                      \
        zt[i][j] += __shfl_xor_sync(0xffffffffu, zt[i][j], m);            \
} while (0)

extern "C" __global__ void __launch_bounds__(T1, 1)
arf_fused(const float* __restrict__ x1, const float* __restrict__ x2,
          const float* __restrict__ x3,
          const float* __restrict__ f1, const float* __restrict__ f2g,
          const float* __restrict__ f3, const float* __restrict__ fout,
          float* __restrict__ out)
{
    extern __shared__ __align__(16) float2 f_s[];   // factors | fout | rings

    const int tid = threadIdx.x;

    // factor repack: f_s[r*NPAIRS + kp] = (f_seg[2k][r], f_seg[2k+1][r])
    for (int idx = tid; idx < FS_ELEMS; idx += T1) {
        int r  = idx / NPAIRS;
        int kp = idx % NPAIRS;
        const float* f; int kloc;
        if (kp < K1 / 2)              { f = f1;  kloc = 2 * kp; }
        else if (kp < (K1 + K2) / 2)  { f = f2g; kloc = 2 * (kp - K1 / 2); }
        else                          { f = f3;  kloc = 2 * (kp - (K1 + K2) / 2); }
        f_s[idx] = make_float2(f[kloc * RANK + r], f[(kloc + 1) * RANK + r]);
    }
    // fout: raw float2 view (rank pairs), after the factor area
    float2* fo_s = f_s + FS_ELEMS;
    const float2* fo_g = reinterpret_cast<const float2*>(fout);
    for (int idx = tid; idx < FO_ELEMS; idx += T1) fo_s[idx] = fo_g[idx];
    __syncthreads();

    const ulonglong2* fsp  = reinterpret_cast<const ulonglong2*>(f_s);
    const u64*        fo64 = reinterpret_cast<const u64*>(fo_s);

    const int lane = tid & 31;
    const int kL   = lane & 15;
    const int h    = lane >> 4;            // half-warp: owns rows 2h, 2h+1
    const int wid  = tid >> 5;
    const int gw   = blockIdx.x * (T1 / 32) + wid;

    const uint32_t stage_base =
        (uint32_t)__cvta_generic_to_shared((char*)f_s + FS_BYTES + FO_BYTES
                                           + wid * RING_BYTES);
    const uint32_t dstoff = (uint32_t)(h * 512 + kL * 16);

    // factor bases (ulonglong2 units) for this lane's k position
    const ulonglong2* FA = fsp + kL;                          // seg1
    const ulonglong2* FB = FA + (K1 / 2) / 2;                 // seg2 (+256)
    const ulonglong2* FC = FA + ((K1 + K2) / 2) / 2;          // seg3 (+384)

    u64 acc[2][RANK];
#pragma unroll
    for (int i = 0; i < 2; i++)
#pragma unroll
        for (int j = 0; j < RANK; j++) acc[i][j] = 0ull;

    float p[2][RANK], zt[2][RANK];

    // prologue: first group's x1 chunks 0..2 into slots 0..2
    const char* rA  = (const char*)x1 + ((size_t)(gw * 4 + 2 * h) * K1) * 4 + kL * 16;
    const char* rA2 = rA + (size_t)K1 * 4;
    ISSUE(rA, rA2, 0, 0);
    ISSUE(rA, rA2, 1, 1);
    ISSUE(rA, rA2, 2, 2);

    for (int g = gw; g < NGROUPS; g += NWARPS) {
        const int row0 = g * 4;
        const int gn   = (g + NWARPS < NGROUPS) ? g + NWARPS : g;

        const char* rB  = (const char*)x2 + ((size_t)(row0 + 2 * h) * K2) * 4 + kL * 16;
        const char* rB2 = rB + (size_t)K2 * 4;
        const char* rC  = (const char*)x3 + ((size_t)(row0 + 2 * h) * K3) * 4 + kL * 16;
        const char* rC2 = rC + (size_t)K3 * 4;
        const char* rN  = (const char*)x1 + ((size_t)(gn * 4 + 2 * h) * K1) * 4 + kL * 16;
        const char* rN2 = rN + (size_t)K1 * 4;

        // ---- segment 1 (x1): chunks 0..15 ----
#pragma unroll
        for (int c = 0; c < NC1; c++) {
            WAITG2();
            CONSUME(c & 3, FA + c * 16);
            if (c < NC1 - 3) ISSUE(rA, rA2, c + 3,       (c + 3) & 3);
            else             ISSUE(rB, rB2, c - (NC1-3), (c + 3) & 3);
        }
        FOLD(); REDUCE();                      // pipeline stays full underneath
#pragma unroll
        for (int i = 0; i < 2; i++)
#pragma unroll
            for (int j = 0; j < RANK; j++) p[i][j] = zt[i][j];

        // ---- segment 2 (x2) ----
#pragma unroll
        for (int c = 0; c < NC2; c++) {
            WAITG2();
            CONSUME((NC1 + c) & 3, FB + c * 16);
            if (c < NC2 - 3) ISSUE(rB, rB2, c + 3,       (NC1 + c + 3) & 3);
            else             ISSUE(rC, rC2, c - (NC2-3), (NC1 + c + 3) & 3);
        }
        FOLD(); REDUCE();
#pragma unroll
        for (int i = 0; i < 2; i++)
#pragma unroll
            for (int j = 0; j < RANK; j++) p[i][j] *= zt[i][j];

        // ---- segment 3 (x3): leads into next group's x1 ----
#pragma unroll
        for (int c = 0; c < NC3; c++) {
            WAITG2();
            CONSUME((NC1 + NC2 + c) & 3, FC + c * 16);
            if (c < NC3 - 3) ISSUE(rC, rC2, c + 3,       (NC1 + NC2 + c + 3) & 3);
            else             ISSUE(rN, rN2, c - (NC3-3), (NC1 + NC2 + c + 3) & 3);
        }
        FOLD(); REDUCE();
#pragma unroll
        for (int i = 0; i < 2; i++)
#pragma unroll
            for (int j = 0; j < RANK; j++) p[i][j] *= zt[i][j];

        rA = rN; rA2 = rN2;

        // ---- fused epilogue: out[rows 2h, 2h+1] = p @ fout^T ----
        // Lane kL owns cols c = kL + 16*i  (stride-1 across lanes).
        // fo64 addr = c*5+j -> bank = (10*kL + 2j) mod 32: all 16 lanes
        // distinct, halves read identical addresses -> broadcast dedup.
        // Runs while the next group's 3 chunks are in flight.
        u64 yp0[RANK / 2], yp1[RANK / 2];
#pragma unroll
        for (int j = 0; j < RANK / 2; j++) {
            yp0[j] = pk2(p[0][2 * j], p[0][2 * j + 1]);
            yp1[j] = pk2(p[1][2 * j], p[1][2 * j + 1]);
        }
        float* o0 = out + (size_t)(row0 + 2 * h) * OUTDIM;
        float* o1 = o0 + OUTDIM;
#pragma unroll 8
        for (int i = 0; i < OUTDIM / 16; i++) {
            const int c = 16 * i + kL;
            u64 a0 = 0ull, a1 = 0ull;
#pragma unroll
            for (int j = 0; j < RANK / 2; j++) {
                u64 fv = fo64[c * (RANK / 2) + j];  // conflict-free LDS.64
                a0 = fma2(yp0[j], fv, a0);
                a1 = fma2(yp1[j], fv, a1);
            }
            o0[c] = hadd2(a0);    // coalesced STG.32 per half-warp
            o1[c] = hadd2(a1);
        }
    }

    asm volatile("cp.async.wait_group 0;" ::: "memory");   // drain
}

extern "C" void kernel_launch(void* const* d_in, const int* in_sizes, int n_in,
                              void* d_out, int out_size)
{
    const float* x1   = (const float*)d_in[0];
    const float* x2   = (const float*)d_in[1];
    const float* x3   = (const float*)d_in[2];
    const float* f1   = (const float*)d_in[3];
    const float* f2   = (const float*)d_in[4];
    const float* f3   = (const float*)d_in[5];
    const float* fout = (const float*)d_in[6];
    float* out = (float*)d_out;

    cudaFuncSetAttribute(arf_fused,
                         cudaFuncAttributeMaxDynamicSharedMemorySize, SMEM1);

    arf_fused<<<GRID1, T1, SMEM1>>>(x1, x2, x3, f1, f2, f3, fout, out);
}

// round 17
// speedup vs baseline: 1.2255x; 1.1390x over previous
#include <cuda_runtime.h>
#include <cstdint>

// Problem constants
#define B_ROWS   65536
#define K1       1024
#define K2       512
#define K3       768
#define NPAIRS   1152                  // (K1+K2+K3)/2
#define RANK     10
#define OUTDIM   512

#define T1       384                   // 12 warps, 1 CTA/SM
#define GRID1    152
#define NWARPS   (GRID1 * (T1 / 32))   // 1824
#define ROWS_PER_GROUP 8
#define NGROUPS  (B_ROWS / ROWS_PER_GROUP)   // 8192

#define FS_ELEMS (RANK * NPAIRS)       // 11520 float2
#define FS_BYTES (FS_ELEMS * 8)        // 92160
#define FO_ELEMS (OUTDIM * (RANK / 2)) // 2560 u64
#define FO_BYTES (FO_ELEMS * 8)        // 20480
#define RING_BYTES 8192                // 4 slots x 2KB per warp
#define SMEM1    (FS_BYTES + FO_BYTES + (T1 / 32) * RING_BYTES)  // 210944

// chunk counts (64-float / 256-byte chunks per row)
#define NC1      (K1 / 64)             // 16
#define NC2      (K2 / 64)             // 8
#define NC3      (K3 / 64)             // 12

typedef unsigned long long u64;

// dynamic work-queue counter (reset by arf_reset each launch)
__device__ int g_ctr;

// ---------- f32x2 packed helpers ----------
__device__ __forceinline__ u64 pk2(float lo, float hi) {
    u64 r; asm("mov.b64 %0, {%1, %2};" : "=l"(r) : "f"(lo), "f"(hi)); return r;
}
__device__ __forceinline__ void upk2(u64 v, float& lo, float& hi) {
    asm("mov.b64 {%0, %1}, %2;" : "=f"(lo), "=f"(hi) : "l"(v));
}
__device__ __forceinline__ u64 fma2(u64 a, u64 b, u64 c) {
    u64 d; asm("fma.rn.f32x2 %0, %1, %2, %3;" : "=l"(d) : "l"(a), "l"(b), "l"(c));
    return d;
}
__device__ __forceinline__ float hadd2(u64 v) {
    float lo, hi; upk2(v, lo, hi); return lo + hi;
}
__device__ __forceinline__ ulonglong2 lds128(uint32_t a) {
    ulonglong2 v;
    asm volatile("ld.shared.v2.u64 {%0, %1}, [%2];"
                 : "=l"(v.x), "=l"(v.y) : "r"(a));
    return v;
}

#define CP16(DST, SRC) \
    asm volatile("cp.async.cg.shared.global [%0], [%1], 16;" \
                 :: "r"(DST), "l"(SRC) : "memory")

// issue one 2KB chunk (8 rows x 256B): this lane copies 16B for each of its
// half's 4 rows (rows 4h..4h+3). BASE = &x[(row0+4h)*K] + kL*16 (char*),
// KB4 = row stride in bytes. Then commit a group.
#define ISSUE(BASE, KB4, C, SLOT) do {                                    \
    uint32_t _d = stage_base + (uint32_t)(SLOT) * 2048u + dstoff;         \
    const char* _s = (BASE) + (size_t)(C) * 256;                          \
    CP16(_d,         _s);                                                 \
    CP16(_d +  256u, _s + (KB4));                                         \
    CP16(_d +  512u, _s + 2 * (KB4));                                     \
    CP16(_d +  768u, _s + 3 * (KB4));                                     \
    asm volatile("cp.async.commit_group;" ::: "memory");                  \
} while (0)

#define WAITG2() asm volatile("cp.async.wait_group 2;" ::: "memory")

// consume ring slot SLOT against factor pointer FP (10 LDS.128 + 80 fma2)
#define CONSUME(SLOT, FP) do {                                            \
    uint32_t _s = stage_base + (uint32_t)(SLOT) * 2048u + dstoff;         \
    ulonglong2 vA = lds128(_s);                                           \
    ulonglong2 vB = lds128(_s + 256u);                                    \
    ulonglong2 vC = lds128(_s + 512u);                                    \
    ulonglong2 vD = lds128(_s + 768u);                                    \
    const ulonglong2* _fp = (FP);                                         \
    _Pragma("unroll")                                                     \
    for (int j = 0; j < RANK; j++) {                                      \
        ulonglong2 fv = _fp[j * (NPAIRS / 2)];                            \
        acc[0][j] = fma2(vA.x, fv.x, acc[0][j]);                          \
        acc[0][j] = fma2(vA.y, fv.y, acc[0][j]);                          \
        acc[1][j] = fma2(vB.x, fv.x, acc[1][j]);                          \
        acc[1][j] = fma2(vB.y, fv.y, acc[1][j]);                          \
        acc[2][j] = fma2(vC.x, fv.x, acc[2][j]);                          \
        acc[2][j] = fma2(vC.y, fv.y, acc[2][j]);                          \
        acc[3][j] = fma2(vD.x, fv.x, acc[3][j]);                          \
        acc[3][j] = fma2(vD.y, fv.y, acc[3][j]);                          \
    }                                                                     \
} while (0)

// fold even/odd halves of acc into zt, zero acc
#define FOLD() do {                                                       \
    _Pragma("unroll") for (int i = 0; i < 4; i++)                         \
    _Pragma("unroll") for (int j = 0; j < RANK; j++) {                    \
        zt[i][j] = hadd2(acc[i][j]); acc[i][j] = 0ull; }                  \
} while (0)

// butterfly-reduce zt over the 16-lane k-group (stays within each half)
#define REDUCE() do {                                                     \
    _Pragma("unroll") for (int m = 8; m > 0; m >>= 1)                     \
    _Pragma("unroll") for (int i = 0; i < 4; i++)                         \
    _Pragma("unroll") for (int j = 0; j < RANK; j++)                      \
        zt[i][j] += __shfl_xor_sync(0xffffffffu, zt[i][j], m);            \
} while (0)

extern "C" __global__ void arf_reset() { g_ctr = NWARPS; }

extern "C" __global__ void __launch_bounds__(T1, 1)
arf_fused(const float* __restrict__ x1, const float* __restrict__ x2,
          const float* __restrict__ x3,
          const float* __restrict__ f1, const float* __restrict__ f2g,
          const float* __restrict__ f3, const float* __restrict__ fout,
          float* __restrict__ out)
{
    extern __shared__ __align__(16) float2 f_s[];   // factors | fout | rings

    const int tid = threadIdx.x;

    // factor repack: f_s[r*NPAIRS + kp] = (f_seg[2k][r], f_seg[2k+1][r])
    for (int idx = tid; idx < FS_ELEMS; idx += T1) {
        int r  = idx / NPAIRS;
        int kp = idx % NPAIRS;
        const float* f; int kloc;
        if (kp < K1 / 2)              { f = f1;  kloc = 2 * kp; }
        else if (kp < (K1 + K2) / 2)  { f = f2g; kloc = 2 * (kp - K1 / 2); }
        else                          { f = f3;  kloc = 2 * (kp - (K1 + K2) / 2); }
        f_s[idx] = make_float2(f[kloc * RANK + r], f[(kloc + 1) * RANK + r]);
    }
    // fout: raw float2 view (rank pairs)
    float2* fo_s = f_s + FS_ELEMS;
    const float2* fo_g = reinterpret_cast<const float2*>(fout);
    for (int idx = tid; idx < FO_ELEMS; idx += T1) fo_s[idx] = fo_g[idx];
    __syncthreads();

    const ulonglong2* fsp  = reinterpret_cast<const ulonglong2*>(f_s);
    const u64*        fo64 = reinterpret_cast<const u64*>(fo_s);

    const int lane = tid & 31;
    const int kL   = lane & 15;
    const int h    = lane >> 4;            // half-warp: owns rows 4h..4h+3
    const int wid  = tid >> 5;
    const int gw   = blockIdx.x * (T1 / 32) + wid;

    const uint32_t stage_base =
        (uint32_t)__cvta_generic_to_shared((char*)f_s + FS_BYTES + FO_BYTES
                                           + wid * RING_BYTES);
    const uint32_t dstoff = (uint32_t)(h * 1024 + kL * 16);

    // factor bases (ulonglong2 units) for this lane's k position
    const ulonglong2* FA = fsp + kL;                          // seg1
    const ulonglong2* FB = FA + (K1 / 2) / 2;                 // seg2 (+256)
    const ulonglong2* FC = FA + ((K1 + K2) / 2) / 2;          // seg3 (+384)

    u64 acc[4][RANK];
#pragma unroll
    for (int i = 0; i < 4; i++)
#pragma unroll
        for (int j = 0; j < RANK; j++) acc[i][j] = 0ull;

    float p[4][RANK], zt[4][RANK];

    int g = gw;   // first group statically assigned; rest via work queue

    // prologue: group g's x1 chunks 0..2 into slots 0..2
    const char* rA = (const char*)x1
                   + ((size_t)(g * ROWS_PER_GROUP + 4 * h) * K1) * 4 + kL * 16;
    ISSUE(rA, K1 * 4, 0, 0);
    ISSUE(rA, K1 * 4, 1, 1);
    ISSUE(rA, K1 * 4, 2, 2);

    while (g < NGROUPS) {
        const int row0 = g * ROWS_PER_GROUP;

        // fetch next group: ONE lane does the atomic, broadcast warp-wide
        // (per-lane atomics would give each lane a different group id)
        int gn;
        if (lane == 0) gn = atomicAdd(&g_ctr, 1);
        gn = __shfl_sync(0xffffffffu, gn, 0);
        const int gl = (gn < NGROUPS) ? gn : g;     // lead target (clamped)

        const char* rB = (const char*)x2 + ((size_t)(row0 + 4 * h) * K2) * 4 + kL * 16;
        const char* rC = (const char*)x3 + ((size_t)(row0 + 4 * h) * K3) * 4 + kL * 16;
        const char* rN = (const char*)x1
                       + ((size_t)(gl * ROWS_PER_GROUP + 4 * h) * K1) * 4 + kL * 16;

        // ---- segment 1 (x1): chunks 0..15 ----
#pragma unroll
        for (int c = 0; c < NC1; c++) {
            WAITG2();
            CONSUME(c & 3, FA + c * 16);
            if (c < NC1 - 3) ISSUE(rA, K1 * 4, c + 3,       (c + 3) & 3);
            else             ISSUE(rB, K2 * 4, c - (NC1-3), (c + 3) & 3);
        }
        FOLD(); REDUCE();                      // pipeline stays full underneath
#pragma unroll
        for (int i = 0; i < 4; i++)
#pragma unroll
            for (int j = 0; j < RANK; j++) p[i][j] = zt[i][j];

        // ---- segment 2 (x2) ----
#pragma unroll
        for (int c = 0; c < NC2; c++) {
            WAITG2();
            CONSUME((NC1 + c) & 3, FB + c * 16);
            if (c < NC2 - 3) ISSUE(rB, K2 * 4, c + 3,       (NC1 + c + 3) & 3);
            else             ISSUE(rC, K3 * 4, c - (NC2-3), (NC1 + c + 3) & 3);
        }
        FOLD(); REDUCE();
#pragma unroll
        for (int i = 0; i < 4; i++)
#pragma unroll
            for (int j = 0; j < RANK; j++) p[i][j] *= zt[i][j];

        // ---- segment 3 (x3): leads into next group's x1 ----
#pragma unroll
        for (int c = 0; c < NC3; c++) {
            WAITG2();
            CONSUME((NC1 + NC2 + c) & 3, FC + c * 16);
            if (c < NC3 - 3) ISSUE(rC, K3 * 4, c + 3,       (NC1 + NC2 + c + 3) & 3);
            else             ISSUE(rN, K1 * 4, c - (NC3-3), (NC1 + NC2 + c + 3) & 3);
        }
        FOLD(); REDUCE();
#pragma unroll
        for (int i = 0; i < 4; i++)
#pragma unroll
            for (int j = 0; j < RANK; j++) p[i][j] *= zt[i][j];

        rA = rN;

        // ---- fused epilogue: out[rows 4h..4h+3] = p @ fout^T ----
        // Lane kL owns cols c = kL + 16*i. fo64 addr = c*5+j ->
        // bank (10*kL + 2j) mod 32: conflict-free, halves broadcast.
        // Runs while the next group's 3 chunks are in flight.
        u64 yp[4][RANK / 2];
#pragma unroll
        for (int i = 0; i < 4; i++)
#pragma unroll
            for (int j = 0; j < RANK / 2; j++)
                yp[i][j] = pk2(p[i][2 * j], p[i][2 * j + 1]);

        float* ob = out + (size_t)(row0 + 4 * h) * OUTDIM;
#pragma unroll 4
        for (int it = 0; it < OUTDIM / 16; it++) {
            const int c = 16 * it + kL;
            u64 a0 = 0ull, a1 = 0ull, a2 = 0ull, a3 = 0ull;
#pragma unroll
            for (int j = 0; j < RANK / 2; j++) {
                u64 fv = fo64[c * (RANK / 2) + j];  // conflict-free LDS.64
                a0 = fma2(yp[0][j], fv, a0);
                a1 = fma2(yp[1][j], fv, a1);
                a2 = fma2(yp[2][j], fv, a2);
                a3 = fma2(yp[3][j], fv, a3);
            }
            ob[c]              = hadd2(a0);    // coalesced STG.32 per half
            ob[c + OUTDIM]     = hadd2(a1);
            ob[c + 2 * OUTDIM] = hadd2(a2);
            ob[c + 3 * OUTDIM] = hadd2(a3);
        }

        g = gn;
    }

    asm volatile("cp.async.wait_group 0;" ::: "memory");   // drain
}

extern "C" void kernel_launch(void* const* d_in, const int* in_sizes, int n_in,
                              void* d_out, int out_size)
{
    const float* x1   = (const float*)d_in[0];
    const float* x2   = (const float*)d_in[1];
    const float* x3   = (const float*)d_in[2];
    const float* f1   = (const float*)d_in[3];
    const float* f2   = (const float*)d_in[4];
    const float* f3   = (const float*)d_in[5];
    const float* fout = (const float*)d_in[6];
    float* out = (float*)d_out;

    cudaFuncSetAttribute(arf_fused,
                         cudaFuncAttributeMaxDynamicSharedMemorySize, SMEM1);

    arf_reset<<<1, 1>>>();
    arf_fused<<<GRID1, T1, SMEM1>>>(x1, x2, x3, f1, f2, f3, fout, out);
}